// round 1
// baseline (speedup 1.0000x reference)
#include <cuda_runtime.h>
#include <cuda_bf16.h>
#include <math.h>

#define BATCH 2
#define DIM   256
#define NC    19
#define TOPK  256
#define HF    128
#define WF    128
#define HH    512
#define WW    512
#define SPIX  (HF*WF)            // 16384
#define NPIX  (BATCH*HH*WW)      // 524288
#define EPSV  1e-12f
#define GAMMA_MAX 0.999f

// ---------------- scratch (static device memory; no allocations) ----------------
__device__ float g_fT[(size_t)BATCH*SPIX*DIM];   // features transposed to [B, HF, WF, DIM]
__device__ float g_cw[(size_t)NC*NPIX];          // per-class weight lists
__device__ int   g_cidx[(size_t)NC*NPIX];        // per-class pixel-index lists
__device__ int   g_cnt[NC];                      // per-class counts (append cursors)
__device__ float g_selw[NC*TOPK];                // selected top-k weights
__device__ int   g_seli[NC*TOPK];                // selected top-k pixel indices
__device__ float g_acc[NC*DIM];                  // weighted feature sums

// ---------------- helpers ----------------
__device__ __forceinline__ void src_coord(int o, int &i0, int &i1, float &f) {
    // output coord o in [0,512) -> source coord (o+0.5)*0.25 - 0.5, clamped bilinear
    float s = (o + 0.5f) * 0.25f - 0.5f;
    float fl = floorf(s);
    f = s - fl;
    int i = (int)fl;
    i0 = min(max(i, 0), HF - 1);
    i1 = min(max(i + 1, 0), HF - 1);
}

// ---------------- kernels ----------------
__global__ void k_init() {
    int t = blockIdx.x * blockDim.x + threadIdx.x;
    if (t < NC) g_cnt[t] = 0;
}

// NCHW -> NHWC transpose of features: g_fT[b][s][d] = f[b][d][s]
__global__ void k_transpose(const float* __restrict__ f) {
    __shared__ float tile[32][33];
    int b  = blockIdx.z;
    int s0 = blockIdx.x * 32;
    int d0 = blockIdx.y * 32;
    #pragma unroll
    for (int i = threadIdx.y; i < 32; i += 8)
        tile[i][threadIdx.x] =
            f[((size_t)(b * DIM + d0 + i)) * SPIX + s0 + threadIdx.x];
    __syncthreads();
    #pragma unroll
    for (int i = threadIdx.y; i < 32; i += 8)
        g_fT[((size_t)(b * SPIX + s0 + i)) * DIM + d0 + threadIdx.x] =
            tile[threadIdx.x][i];
}

// Per-pixel: bilinear weight for its own label class; append (w, pixel) to class list.
__global__ void k_weights(const float* __restrict__ weight,
                          const int* __restrict__ labels) {
    __shared__ int s_cnt[NC];
    __shared__ int s_base[NC];
    int n = blockIdx.x * 256 + threadIdx.x;
    if (threadIdx.x < NC) s_cnt[threadIdx.x] = 0;
    __syncthreads();

    int lab = labels[n];
    bool valid = ((unsigned)lab < NC);
    float w = 0.f;
    int r = 0;
    if (valid) {
        int b   = n >> 18;            // / (512*512)
        int rem = n & (HH * WW - 1);
        int Y = rem >> 9;
        int X = rem & 511;
        int y0, y1, x0, x1; float fy, fx;
        src_coord(Y, y0, y1, fy);
        src_coord(X, x0, x1, fx);
        const float* wp = weight + ((size_t)(b * NC + lab)) * SPIX;
        float v00 = __ldg(wp + y0 * WF + x0);
        float v01 = __ldg(wp + y0 * WF + x1);
        float v10 = __ldg(wp + y1 * WF + x0);
        float v11 = __ldg(wp + y1 * WF + x1);
        w = (1.f - fy) * ((1.f - fx) * v00 + fx * v01)
          +        fy  * ((1.f - fx) * v10 + fx * v11);
        r = atomicAdd(&s_cnt[lab], 1);
    }
    __syncthreads();
    if (threadIdx.x < NC)
        s_base[threadIdx.x] = atomicAdd(&g_cnt[threadIdx.x], s_cnt[threadIdx.x]);
    __syncthreads();
    if (valid) {
        size_t o = (size_t)lab * NPIX + (size_t)(s_base[lab] + r);
        g_cw[o]   = w;
        g_cidx[o] = n;
    }
}

// Exact per-class top-256 via 3-level radix select on float bits (monotone for w>=0).
__global__ void k_select() {
    int c = blockIdx.x;
    int L = g_cnt[c];
    const float* cw = g_cw  + (size_t)c * NPIX;
    const int*   ci = g_cidx + (size_t)c * NPIX;
    float* sw = g_selw + c * TOPK;
    int*   si = g_seli + c * TOPK;
    int t = threadIdx.x, T = blockDim.x;

    if (L <= TOPK) {
        for (int i = t; i < TOPK; i += T) {
            if (i < L) { sw[i] = cw[i]; si[i] = ci[i]; }
            else       { sw[i] = 0.f;   si[i] = 0;     }
        }
        return;
    }

    __shared__ unsigned hist[2048];
    __shared__ int s_sel, s_rem, s_tbin, s_above, s_done;
    __shared__ unsigned s_pmask, s_pval;
    if (t == 0) { s_sel = 0; s_rem = TOPK; s_pmask = 0u; s_pval = 0u; s_done = 0; }
    __syncthreads();

    const int shifts[3] = {21, 10, 0};
    const int nbins[3]  = {2048, 2048, 1024};

    for (int lev = 0; lev < 3; lev++) {
        int sh = shifts[lev];
        unsigned bm = (unsigned)nbins[lev] - 1u;
        for (int i = t; i < 2048; i += T) hist[i] = 0u;
        __syncthreads();
        unsigned pm = s_pmask, pv = s_pval;
        for (int i = t; i < L; i += T) {
            unsigned key = __float_as_uint(cw[i]);
            if ((key & pm) == pv) atomicAdd(&hist[(key >> sh) & bm], 1u);
        }
        __syncthreads();
        if (t == 0) {
            int cum = 0;
            int b = nbins[lev] - 1;
            for (; b >= 0; b--) { cum += (int)hist[b]; if (cum >= s_rem) break; }
            s_tbin  = b;
            s_above = cum - (int)hist[b];
        }
        __syncthreads();
        int tb = s_tbin;
        // gather elements strictly above the threshold bin (all guaranteed in top-k)
        for (int i = t; i < L; i += T) {
            unsigned key = __float_as_uint(cw[i]);
            if ((key & pm) == pv && (int)((key >> sh) & bm) > tb) {
                int p = atomicAdd(&s_sel, 1);
                sw[p] = cw[i]; si[p] = ci[i];
            }
        }
        __syncthreads();
        if (t == 0) {
            s_rem -= s_above;
            s_pval  = pv | ((unsigned)tb << sh);
            s_pmask = pm | (bm << sh);
            if ((int)hist[tb] == s_rem) s_done = 1;  // threshold bin exactly fills the quota
        }
        __syncthreads();
        if (s_done || lev == 2) {
            unsigned fpm = s_pmask, fpv = s_pval;
            for (int i = t; i < L; i += T) {
                unsigned key = __float_as_uint(cw[i]);
                if ((key & fpm) == fpv) {
                    int p = atomicAdd(&s_sel, 1);
                    if (p < TOPK) { sw[p] = cw[i]; si[p] = ci[i]; }
                }
            }
            break;
        }
    }
}

// Weighted feature accumulation: one block per class, 1024 threads.
// thread = (part 0..3, dim 0..255); each part handles 64 selected pixels.
// Deterministic fixed-order reduction (no global float atomics).
__global__ void k_accum() {
    int c = blockIdx.x;
    int t = threadIdx.x;
    int d = t & (DIM - 1);
    int part = t >> 8;
    float acc = 0.f;
    int k0 = part * (TOPK / 4);
    #pragma unroll 4
    for (int k = k0; k < k0 + TOPK / 4; k++) {
        float w = g_selw[c * TOPK + k];
        if (w > 0.f) {
            int n   = g_seli[c * TOPK + k];
            int b   = n >> 18;
            int rem = n & (HH * WW - 1);
            int Y = rem >> 9;
            int X = rem & 511;
            int y0, y1, x0, x1; float fy, fx;
            src_coord(Y, y0, y1, fy);
            src_coord(X, x0, x1, fx);
            const float* base = g_fT + ((size_t)b * SPIX) * DIM;
            const float* p00 = base + ((size_t)(y0 * WF + x0)) * DIM;
            const float* p01 = base + ((size_t)(y0 * WF + x1)) * DIM;
            const float* p10 = base + ((size_t)(y1 * WF + x0)) * DIM;
            const float* p11 = base + ((size_t)(y1 * WF + x1)) * DIM;
            float w00 = (1.f - fy) * (1.f - fx);
            float w01 = (1.f - fy) * fx;
            float w10 = fy * (1.f - fx);
            float w11 = fy * fx;
            float v = w00 * __ldg(p00 + d) + w01 * __ldg(p01 + d)
                    + w10 * __ldg(p10 + d) + w11 * __ldg(p11 + d);
            acc += w * v;
        }
    }
    __shared__ float red[1024];
    red[t] = acc;
    __syncthreads();
    if (t < DIM)
        g_acc[c * DIM + d] = red[d] + red[d + 256] + red[d + 512] + red[d + 768];
}

// Normalize, EMA, final normalize, write output (+ updated counts).
__global__ void k_final(const float* __restrict__ prototypes,
                        const float* __restrict__ update_count,
                        float* __restrict__ out, int out_size) {
    int c = blockIdx.x;
    int d = threadIdx.x;
    __shared__ float red[DIM];

    // wsum = sum of selected weights (TOPK == DIM == 256, one per thread)
    red[d] = g_selw[c * TOPK + d];
    __syncthreads();
    for (int s = DIM / 2; s > 0; s >>= 1) {
        if (d < s) red[d] += red[d + s];
        __syncthreads();
    }
    float wsum = red[0];
    __syncthreads();

    float proto = g_acc[c * DIM + d] / fmaxf(wsum, EPSV);

    red[d] = proto * proto;
    __syncthreads();
    for (int s = DIM / 2; s > 0; s >>= 1) {
        if (d < s) red[d] += red[d + s];
        __syncthreads();
    }
    float nrm = sqrtf(red[0]);
    __syncthreads();
    proto = proto / fmaxf(nrm, EPSV);

    bool has = (g_cnt[c] > 0) && (wsum > 0.f);
    float uc = update_count[c];
    float gamma = (uc == 0.f) ? 0.f : fminf(1.f - 1.f / (uc + 1.f), GAMMA_MAX);
    float oldp = prototypes[c * DIM + d];
    float nv = has ? (gamma * oldp + (1.f - gamma) * proto) : oldp;

    red[d] = nv * nv;
    __syncthreads();
    for (int s = DIM / 2; s > 0; s >>= 1) {
        if (d < s) red[d] += red[d + s];
        __syncthreads();
    }
    float nrm2 = sqrtf(red[0]);
    nv = nv / fmaxf(nrm2, EPSV);

    out[c * DIM + d] = nv;
    if (d == 0 && out_size >= NC * DIM + NC)
        out[NC * DIM + c] = uc + (has ? 1.f : 0.f);
}

// ---------------- launch ----------------
extern "C" void kernel_launch(void* const* d_in, const int* in_sizes, int n_in,
                              void* d_out, int out_size) {
    const float* features     = (const float*)d_in[0];
    const float* weight       = (const float*)d_in[1];
    const float* prototypes   = (const float*)d_in[2];
    const float* update_count = (const float*)d_in[3];
    const int*   labels       = (const int*)d_in[4];
    float* out = (float*)d_out;

    k_init<<<1, 32>>>();
    k_transpose<<<dim3(SPIX / 32, DIM / 32, BATCH), dim3(32, 8)>>>(features);
    k_weights<<<NPIX / 256, 256>>>(weight, labels);
    k_select<<<NC, 512>>>();
    k_accum<<<NC, 1024>>>();
    k_final<<<NC, DIM>>>(prototypes, update_count, out, out_size);
}

// round 2
// speedup vs baseline: 1.0700x; 1.0700x over previous
#include <cuda_runtime.h>
#include <cuda_bf16.h>
#include <math.h>

#define BATCH 2
#define DIM   256
#define NC    19
#define TOPK  256
#define HF    128
#define WF    128
#define HH    512
#define WW    512
#define SPIX  (HF*WF)            // 16384
#define NPIX  (BATCH*HH*WW)      // 524288
#define EPSV  1e-12f
#define GAMMA_MAX 0.999f
#define NB    8192               // histogram bins over w in [0,1)
#define CANDCAP 32768            // per-class candidate capacity (threshold bin)

// ---------------- scratch (static device memory; no allocations) ----------------
__device__ float g_fT[(size_t)BATCH*SPIX*DIM];   // features transposed [B, HF*WF, DIM]
__device__ float g_w[NPIX];                      // per-pixel weight (own label class)
__device__ int   g_hist[NC*NB];                  // per-class weight histograms
__device__ int   g_tb[NC];                       // threshold bin per class
__device__ int   g_above[NC];                    // count strictly above threshold bin
__device__ int   g_cnt[NC];                      // total valid pixels per class
__device__ int   g_scur[NC];                     // selected-list cursors
__device__ int   g_ccnt[NC];                     // candidate counts
__device__ float g_candw[(size_t)NC*CANDCAP];
__device__ int   g_candi[(size_t)NC*CANDCAP];
__device__ float g_selw[NC*TOPK];                // selected top-k weights
__device__ int   g_seli[NC*TOPK];                // selected top-k pixel indices
__device__ float g_acc[NC*DIM];                  // weighted feature sums

// ---------------- helpers ----------------
__device__ __forceinline__ void src_coord(int o, int &i0, int &i1, float &f) {
    float s = (o + 0.5f) * 0.25f - 0.5f;
    float fl = floorf(s);
    f = s - fl;
    int i = (int)fl;
    i0 = min(max(i, 0), HF - 1);
    i1 = min(max(i + 1, 0), HF - 1);
}

__device__ __forceinline__ int w_bin(float w) {
    int b = (int)(w * (float)NB);
    return min(NB - 1, max(0, b));
}

// ---------------- kernels ----------------
__global__ void k_zero() {
    int t = blockIdx.x * blockDim.x + threadIdx.x;
    if (t < NC * NB) g_hist[t] = 0;
    if (t < NC) { g_scur[t] = 0; g_ccnt[t] = 0; }
}

// NCHW -> NHWC transpose of features
__global__ void k_transpose(const float* __restrict__ f) {
    __shared__ float tile[32][33];
    int b  = blockIdx.z;
    int s0 = blockIdx.x * 32;
    int d0 = blockIdx.y * 32;
    #pragma unroll
    for (int i = threadIdx.y; i < 32; i += 8)
        tile[i][threadIdx.x] =
            f[((size_t)(b * DIM + d0 + i)) * SPIX + s0 + threadIdx.x];
    __syncthreads();
    #pragma unroll
    for (int i = threadIdx.y; i < 32; i += 8)
        g_fT[((size_t)(b * SPIX + s0 + i)) * DIM + d0 + threadIdx.x] =
            tile[threadIdx.x][i];
}

// Pass 1: per-pixel bilinear weight for own label; store + histogram (warp-aggregated).
__global__ void k_weights(const float* __restrict__ weight,
                          const int* __restrict__ labels) {
    int n = blockIdx.x * 256 + threadIdx.x;
    int lab = labels[n];
    bool valid = ((unsigned)lab < NC);
    float w = 0.f;
    int key = 0;
    if (valid) {
        int b   = n >> 18;
        int rem = n & (HH * WW - 1);
        int Y = rem >> 9;
        int X = rem & 511;
        int y0, y1, x0, x1; float fy, fx;
        src_coord(Y, y0, y1, fy);
        src_coord(X, x0, x1, fx);
        const float* wp = weight + ((size_t)(b * NC + lab)) * SPIX;
        float v00 = __ldg(wp + y0 * WF + x0);
        float v01 = __ldg(wp + y0 * WF + x1);
        float v10 = __ldg(wp + y1 * WF + x0);
        float v11 = __ldg(wp + y1 * WF + x1);
        w = (1.f - fy) * ((1.f - fx) * v00 + fx * v01)
          +        fy  * ((1.f - fx) * v10 + fx * v11);
        g_w[n] = w;
        key = lab * NB + w_bin(w);
    }
    // warp-aggregated histogram atomics
    unsigned am = __ballot_sync(0xFFFFFFFFu, valid);
    if (valid) {
        unsigned grp = __match_any_sync(am, key);
        int leader = __ffs(grp) - 1;
        if ((threadIdx.x & 31) == leader)
            atomicAdd(&g_hist[key], __popc(grp));
    }
}

// Per-class threshold-bin discovery from the histogram (19 tiny blocks).
__global__ void k_thresh() {
    int c = blockIdx.x;
    int t = threadIdx.x;               // 256 threads
    const int CH = NB / 256;           // 32 bins/chunk, chunk 0 = highest bins
    __shared__ int csum[256];
    __shared__ int pre[257];
    const int* h = g_hist + c * NB;
    int lo = NB - (t + 1) * CH;
    int s = 0;
    #pragma unroll
    for (int b = 0; b < CH; b++) s += h[lo + b];
    csum[t] = s;
    __syncthreads();
    if (t == 0) {
        int cum = 0;
        pre[0] = 0;
        for (int i = 0; i < 256; i++) { cum += csum[i]; pre[i + 1] = cum; }
        int total = cum;
        g_cnt[c] = total;
        if (total <= TOPK) {
            g_tb[c] = -1;
            g_above[c] = total;
        } else {
            int i = 0;
            while (pre[i + 1] < TOPK) i++;
            int acc = pre[i];
            int b = NB - i * CH - 1;
            int tb = b;
            for (; b >= NB - (i + 1) * CH; b--) {
                acc += h[b];
                if (acc >= TOPK) { tb = b; break; }
            }
            g_tb[c] = tb;
            g_above[c] = acc - h[tb];
        }
    }
}

// Pass 2: partition pixels into selected (bin > tb) and candidates (bin == tb).
__global__ void k_part(const int* __restrict__ labels) {
    int n = blockIdx.x * 256 + threadIdx.x;
    int lab = labels[n];
    if ((unsigned)lab >= NC) return;
    float w = g_w[n];
    int bin = w_bin(w);
    int tb = g_tb[lab];
    if (bin > tb) {
        int p = atomicAdd(&g_scur[lab], 1);
        g_selw[lab * TOPK + p] = w;
        g_seli[lab * TOPK + p] = n;
    } else if (bin == tb) {
        int p = atomicAdd(&g_ccnt[lab], 1);
        if (p < CANDCAP) {
            g_candw[(size_t)lab * CANDCAP + p] = w;
            g_candi[(size_t)lab * CANDCAP + p] = n;
        }
    }
}

// Exact top-r select within the (tiny) threshold-bin candidate list per class.
__global__ void k_fill() {
    int c = blockIdx.x;
    int above = g_above[c];
    int r = TOPK - above;
    if (r <= 0) return;
    int L = min(g_ccnt[c], CANDCAP);
    float* sw = g_selw + c * TOPK + above;
    int*   si = g_seli + c * TOPK + above;
    const float* cw = g_candw + (size_t)c * CANDCAP;
    const int*   ci = g_candi + (size_t)c * CANDCAP;
    int t = threadIdx.x, T = blockDim.x;

    if (L <= r) {
        for (int i = t; i < r; i += T) {
            if (i < L) { sw[i] = cw[i]; si[i] = ci[i]; }
            else       { sw[i] = 0.f;   si[i] = 0;     }
        }
        return;
    }

    __shared__ unsigned hist[2048];
    __shared__ int s_sel, s_rem, s_tbin, s_abv, s_done;
    __shared__ unsigned s_pmask, s_pval;
    if (t == 0) { s_sel = 0; s_rem = r; s_pmask = 0u; s_pval = 0u; s_done = 0; }
    __syncthreads();

    const int shifts[3] = {21, 10, 0};
    const int nbins[3]  = {2048, 2048, 1024};

    for (int lev = 0; lev < 3; lev++) {
        int sh = shifts[lev];
        unsigned bm = (unsigned)nbins[lev] - 1u;
        for (int i = t; i < 2048; i += T) hist[i] = 0u;
        __syncthreads();
        unsigned pm = s_pmask, pv = s_pval;
        for (int i = t; i < L; i += T) {
            unsigned key = __float_as_uint(cw[i]);
            if ((key & pm) == pv) atomicAdd(&hist[(key >> sh) & bm], 1u);
        }
        __syncthreads();
        if (t == 0) {
            int cum = 0;
            int b = nbins[lev] - 1;
            for (; b >= 0; b--) { cum += (int)hist[b]; if (cum >= s_rem) break; }
            s_tbin = b;
            s_abv  = cum - (int)hist[b];
        }
        __syncthreads();
        int tb = s_tbin;
        for (int i = t; i < L; i += T) {
            unsigned key = __float_as_uint(cw[i]);
            if ((key & pm) == pv && (int)((key >> sh) & bm) > tb) {
                int p = atomicAdd(&s_sel, 1);
                sw[p] = cw[i]; si[p] = ci[i];
            }
        }
        __syncthreads();
        if (t == 0) {
            s_rem -= s_abv;
            s_pval  = pv | ((unsigned)tb << sh);
            s_pmask = pm | (bm << sh);
            if ((int)hist[tb] == s_rem) s_done = 1;
        }
        __syncthreads();
        if (s_done || lev == 2) {
            unsigned fpm = s_pmask, fpv = s_pval;
            int cap = r;
            for (int i = t; i < L; i += T) {
                unsigned key = __float_as_uint(cw[i]);
                if ((key & fpm) == fpv) {
                    int p = atomicAdd(&s_sel, 1);
                    if (p < cap) { sw[p] = cw[i]; si[p] = ci[i]; }
                }
            }
            break;
        }
    }
}

// Weighted feature accumulation: one block per class, 1024 threads.
__global__ void k_accum() {
    int c = blockIdx.x;
    int t = threadIdx.x;
    int d = t & (DIM - 1);
    int part = t >> 8;
    float acc = 0.f;
    int k0 = part * (TOPK / 4);
    #pragma unroll 4
    for (int k = k0; k < k0 + TOPK / 4; k++) {
        float w = g_selw[c * TOPK + k];
        if (w > 0.f) {
            int n   = g_seli[c * TOPK + k];
            int b   = n >> 18;
            int rem = n & (HH * WW - 1);
            int Y = rem >> 9;
            int X = rem & 511;
            int y0, y1, x0, x1; float fy, fx;
            src_coord(Y, y0, y1, fy);
            src_coord(X, x0, x1, fx);
            const float* base = g_fT + ((size_t)b * SPIX) * DIM;
            const float* p00 = base + ((size_t)(y0 * WF + x0)) * DIM;
            const float* p01 = base + ((size_t)(y0 * WF + x1)) * DIM;
            const float* p10 = base + ((size_t)(y1 * WF + x0)) * DIM;
            const float* p11 = base + ((size_t)(y1 * WF + x1)) * DIM;
            float w00 = (1.f - fy) * (1.f - fx);
            float w01 = (1.f - fy) * fx;
            float w10 = fy * (1.f - fx);
            float w11 = fy * fx;
            float v = w00 * __ldg(p00 + d) + w01 * __ldg(p01 + d)
                    + w10 * __ldg(p10 + d) + w11 * __ldg(p11 + d);
            acc += w * v;
        }
    }
    __shared__ float red[1024];
    red[t] = acc;
    __syncthreads();
    if (t < DIM)
        g_acc[c * DIM + d] = red[d] + red[d + 256] + red[d + 512] + red[d + 768];
}

// Normalize, EMA, final normalize, write output (+ updated counts).
__global__ void k_final(const float* __restrict__ prototypes,
                        const float* __restrict__ update_count,
                        float* __restrict__ out, int out_size) {
    int c = blockIdx.x;
    int d = threadIdx.x;
    __shared__ float red[DIM];

    red[d] = g_selw[c * TOPK + d];
    __syncthreads();
    for (int s = DIM / 2; s > 0; s >>= 1) {
        if (d < s) red[d] += red[d + s];
        __syncthreads();
    }
    float wsum = red[0];
    __syncthreads();

    float proto = g_acc[c * DIM + d] / fmaxf(wsum, EPSV);

    red[d] = proto * proto;
    __syncthreads();
    for (int s = DIM / 2; s > 0; s >>= 1) {
        if (d < s) red[d] += red[d + s];
        __syncthreads();
    }
    float nrm = sqrtf(red[0]);
    __syncthreads();
    proto = proto / fmaxf(nrm, EPSV);

    bool has = (g_cnt[c] > 0) && (wsum > 0.f);
    float uc = update_count[c];
    float gamma = (uc == 0.f) ? 0.f : fminf(1.f - 1.f / (uc + 1.f), GAMMA_MAX);
    float oldp = prototypes[c * DIM + d];
    float nv = has ? (gamma * oldp + (1.f - gamma) * proto) : oldp;

    red[d] = nv * nv;
    __syncthreads();
    for (int s = DIM / 2; s > 0; s >>= 1) {
        if (d < s) red[d] += red[d + s];
        __syncthreads();
    }
    float nrm2 = sqrtf(red[0]);
    nv = nv / fmaxf(nrm2, EPSV);

    out[c * DIM + d] = nv;
    if (d == 0 && out_size >= NC * DIM + NC)
        out[NC * DIM + c] = uc + (has ? 1.f : 0.f);
}

// ---------------- launch ----------------
extern "C" void kernel_launch(void* const* d_in, const int* in_sizes, int n_in,
                              void* d_out, int out_size) {
    const float* features     = (const float*)d_in[0];
    const float* weight       = (const float*)d_in[1];
    const float* prototypes   = (const float*)d_in[2];
    const float* update_count = (const float*)d_in[3];
    const int*   labels       = (const int*)d_in[4];
    float* out = (float*)d_out;

    k_zero<<<(NC * NB + 255) / 256, 256>>>();
    k_transpose<<<dim3(SPIX / 32, DIM / 32, BATCH), dim3(32, 8)>>>(features);
    k_weights<<<NPIX / 256, 256>>>(weight, labels);
    k_thresh<<<NC, 256>>>();
    k_part<<<NPIX / 256, 256>>>(labels);
    k_fill<<<NC, 512>>>();
    k_accum<<<NC, 1024>>>();
    k_final<<<NC, DIM>>>(prototypes, update_count, out, out_size);
}

// round 3
// speedup vs baseline: 1.0817x; 1.0109x over previous
#include <cuda_runtime.h>
#include <cuda_bf16.h>
#include <math.h>

#define BATCH 2
#define DIM   256
#define NC    19
#define TOPK  256
#define HF    128
#define WF    128
#define HH    512
#define WW    512
#define SPIX  (HF*WF)            // 16384
#define NPIX  (BATCH*HH*WW)      // 524288
#define EPSV  1e-12f
#define GAMMA_MAX 0.999f
#define NB    8192               // histogram bins over w in [0,1)
#define CCAP  2048               // shared candidate capacity (threshold bin)

#define TRANS_BLOCKS 8192        // 512 * 8 * 2
#define WT_BLOCKS    2048        // NPIX / 256

// ---------------- scratch (static device memory; zero-init at load) ----------------
__device__ float g_fT[(size_t)BATCH*SPIX*DIM];   // features transposed [B, HF*WF, DIM]
__device__ float g_cw[(size_t)NC*NPIX];          // per-class weight lists
__device__ int   g_cidx[(size_t)NC*NPIX];        // per-class pixel-index lists
__device__ int   g_hist[NC*NB];                  // per-class weight histograms
__device__ int   g_cnt[NC];                      // per-class list counts
__device__ int   g_tb[NC];                       // threshold bin per class

// ---------------- helpers ----------------
__device__ __forceinline__ void src_coord(int o, int &i0, int &i1, float &f) {
    float s = (o + 0.5f) * 0.25f - 0.5f;
    float fl = floorf(s);
    f = s - fl;
    int i = (int)fl;
    i0 = min(max(i, 0), HF - 1);
    i1 = min(max(i + 1, 0), HF - 1);
}

__device__ __forceinline__ int w_bin(float w) {
    int b = (int)(w * (float)NB);
    return min(NB - 1, max(0, b));
}

// ================= K1: fused transpose + weights/list/histogram =================
__global__ void k_main(const float* __restrict__ f,
                       const float* __restrict__ weight,
                       const int* __restrict__ labels) {
    if (blockIdx.x < TRANS_BLOCKS) {
        // ---- NCHW -> NHWC transpose ----
        __shared__ float tile[32][33];
        int i = blockIdx.x;
        int s0 = (i & 511) * 32;
        int d0 = ((i >> 9) & 7) * 32;
        int b  = i >> 12;
        int tx = threadIdx.x & 31;
        int ty = threadIdx.x >> 5;           // 0..7
        #pragma unroll
        for (int r = ty; r < 32; r += 8)
            tile[r][tx] = f[((size_t)(b * DIM + d0 + r)) * SPIX + s0 + tx];
        __syncthreads();
        #pragma unroll
        for (int r = ty; r < 32; r += 8)
            g_fT[((size_t)(b * SPIX + s0 + r)) * DIM + d0 + tx] = tile[tx][r];
    } else {
        // ---- per-pixel weight + per-class list append + histogram ----
        __shared__ int s_cnt[NC];
        __shared__ int s_base[NC];
        int n = (blockIdx.x - TRANS_BLOCKS) * 256 + threadIdx.x;
        if (threadIdx.x < NC) s_cnt[threadIdx.x] = 0;
        __syncthreads();

        int lab = labels[n];
        bool valid = ((unsigned)lab < NC);
        float w = 0.f;
        int r = 0, key = 0;
        if (valid) {
            int b   = n >> 18;
            int rem = n & (HH * WW - 1);
            int Y = rem >> 9;
            int X = rem & 511;
            int y0, y1, x0, x1; float fy, fx;
            src_coord(Y, y0, y1, fy);
            src_coord(X, x0, x1, fx);
            const float* wp = weight + ((size_t)(b * NC + lab)) * SPIX;
            float v00 = __ldg(wp + y0 * WF + x0);
            float v01 = __ldg(wp + y0 * WF + x1);
            float v10 = __ldg(wp + y1 * WF + x0);
            float v11 = __ldg(wp + y1 * WF + x1);
            w = (1.f - fy) * ((1.f - fx) * v00 + fx * v01)
              +        fy  * ((1.f - fx) * v10 + fx * v11);
            r = atomicAdd(&s_cnt[lab], 1);
            key = lab * NB + w_bin(w);
        }
        // warp-aggregated histogram atomics
        unsigned am = __ballot_sync(0xFFFFFFFFu, valid);
        if (valid) {
            unsigned grp = __match_any_sync(am, key);
            int leader = __ffs(grp) - 1;
            if ((threadIdx.x & 31) == leader)
                atomicAdd(&g_hist[key], __popc(grp));
        }
        __syncthreads();
        if (threadIdx.x < NC && s_cnt[threadIdx.x] > 0)
            s_base[threadIdx.x] = atomicAdd(&g_cnt[threadIdx.x], s_cnt[threadIdx.x]);
        __syncthreads();
        if (valid) {
            size_t o = (size_t)lab * NPIX + (size_t)(s_base[lab] + r);
            g_cw[o]   = w;
            g_cidx[o] = n;
        }
    }
}

// ================= K2: threshold bin from histogram + hist cleanup =================
__global__ void k_thresh() {
    int c = blockIdx.x;
    int t = threadIdx.x;                 // 256 threads, 32 bins each (top-down)
    __shared__ int P[256];
    __shared__ int s_j;
    int* h = g_hist + c * NB;
    int lo = NB - (t + 1) * 32;
    int s = 0;
    #pragma unroll
    for (int b = 0; b < 32; b++) s += h[lo + b];
    P[t] = s;
    __syncthreads();
    // inclusive scan over 256 chunk sums (descending-bin order)
    for (int off = 1; off < 256; off <<= 1) {
        int v = (t >= off) ? P[t - off] : 0;
        __syncthreads();
        P[t] += v;
        __syncthreads();
    }
    int total = g_cnt[c];
    if (total <= TOPK) {
        if (t == 0) g_tb[c] = -1;        // take everything
    } else {
        if (P[t] >= TOPK && (t == 0 || P[t - 1] < TOPK)) s_j = t;
        __syncthreads();
        if (t == 0) {
            int j = s_j;
            int acc = (j == 0) ? 0 : P[j - 1];
            for (int b = NB - 32 * j - 1; b >= NB - 32 * (j + 1); b--) {
                acc += h[b];
                if (acc >= TOPK) { g_tb[c] = b; break; }
            }
        }
    }
    __syncthreads();
    // cleanup for next graph replay
    for (int i = t; i < NB; i += 256) h[i] = 0;
}

// ================= K3: partition + fill + accumulate + finalize =================
__global__ void __launch_bounds__(1024) k_tail(
        const float* __restrict__ prototypes,
        const float* __restrict__ update_count,
        float* __restrict__ out, int out_size) {
    int c = blockIdx.x;
    int t = threadIdx.x;
    __shared__ float s_w[TOPK];
    __shared__ int   s_i[TOPK];
    __shared__ float s_cw[CCAP];
    __shared__ int   s_ci[CCAP];
    __shared__ unsigned hist[2048];
    __shared__ float red[1024];
    __shared__ float red2[256];
    __shared__ int s_nsel, s_ncand;
    __shared__ int s_rem, s_tbin, s_abv, s_done;
    __shared__ unsigned s_pmask, s_pval;

    int L  = g_cnt[c];
    int tb = g_tb[c];
    if (t == 0) { s_nsel = 0; s_ncand = 0; }
    __syncthreads();

    // ---- phase A: scan class list, partition ----
    const float* cw = g_cw  + (size_t)c * NPIX;
    const int*   ci = g_cidx + (size_t)c * NPIX;
    for (int i = t; i < L; i += 1024) {
        float w = cw[i];
        int bin = w_bin(w);
        if (bin > tb) {
            int p = atomicAdd(&s_nsel, 1);
            if (p < TOPK) { s_w[p] = w; s_i[p] = ci[i]; }
        } else if (bin == tb) {
            int q = atomicAdd(&s_ncand, 1);
            if (q < CCAP) { s_cw[q] = w; s_ci[q] = ci[i]; }
        }
    }
    __syncthreads();

    // ---- phase B: fill remaining slots from threshold-bin candidates ----
    int above = min(s_nsel, TOPK);
    int r = TOPK - above;
    int L2 = min(s_ncand, CCAP);
    if (r > 0) {
        if (L2 <= r) {
            for (int i = t; i < L2; i += 1024) {
                s_w[above + i] = s_cw[i];
                s_i[above + i] = s_ci[i];
            }
            if (t == 0) s_nsel = above + L2;
            __syncthreads();
        } else {
            // exact top-r via 3-level radix select on float bits (w >= 0)
            if (t == 0) { s_rem = r; s_pmask = 0u; s_pval = 0u; s_done = 0; }
            __syncthreads();
            const int shifts[3] = {21, 10, 0};
            const int nbins[3]  = {2048, 2048, 1024};
            for (int lev = 0; lev < 3; lev++) {
                int sh = shifts[lev];
                unsigned bm = (unsigned)nbins[lev] - 1u;
                for (int i = t; i < 2048; i += 1024) hist[i] = 0u;
                __syncthreads();
                unsigned pm = s_pmask, pv = s_pval;
                for (int i = t; i < L2; i += 1024) {
                    unsigned key = __float_as_uint(s_cw[i]);
                    if ((key & pm) == pv) atomicAdd(&hist[(key >> sh) & bm], 1u);
                }
                __syncthreads();
                if (t == 0) {
                    int cum = 0;
                    int b = nbins[lev] - 1;
                    for (; b >= 0; b--) { cum += (int)hist[b]; if (cum >= s_rem) break; }
                    s_tbin = b;
                    s_abv  = cum - (int)hist[b];
                }
                __syncthreads();
                int tbin = s_tbin;
                for (int i = t; i < L2; i += 1024) {
                    unsigned key = __float_as_uint(s_cw[i]);
                    if ((key & pm) == pv && (int)((key >> sh) & bm) > tbin) {
                        int p = atomicAdd(&s_nsel, 1);
                        if (p < TOPK) { s_w[p] = s_cw[i]; s_i[p] = s_ci[i]; }
                    }
                }
                __syncthreads();
                if (t == 0) {
                    s_rem -= s_abv;
                    s_pval  = s_pval | ((unsigned)tbin << sh);
                    s_pmask = s_pmask | (bm << sh);
                    if ((int)hist[tbin] == s_rem) s_done = 1;
                }
                __syncthreads();
                if (s_done || lev == 2) {
                    unsigned fpm = s_pmask, fpv = s_pval;
                    for (int i = t; i < L2; i += 1024) {
                        unsigned key = __float_as_uint(s_cw[i]);
                        if ((key & fpm) == fpv) {
                            int p = atomicAdd(&s_nsel, 1);
                            if (p < TOPK) { s_w[p] = s_cw[i]; s_i[p] = s_ci[i]; }
                        }
                    }
                    break;
                }
            }
            __syncthreads();
        }
    }

    // ---- phase C: pad + weight sum ----
    int nsel = min(s_nsel, TOPK);
    for (int i = t; i < TOPK; i += 1024)
        if (i >= nsel) { s_w[i] = 0.f; s_i[i] = 0; }
    __syncthreads();
    red[t] = (t < TOPK) ? s_w[t] : 0.f;
    __syncthreads();
    for (int s = 512; s > 0; s >>= 1) {
        if (t < s) red[t] += red[t + s];
        __syncthreads();
    }
    float wsum = red[0];
    __syncthreads();

    // ---- phase D: weighted feature accumulation ----
    int d    = t & (DIM - 1);
    int part = t >> 8;
    float acc = 0.f;
    int k0 = part * (TOPK / 4);
    #pragma unroll 4
    for (int k = k0; k < k0 + TOPK / 4; k++) {
        float w = s_w[k];
        if (w > 0.f) {
            int n   = s_i[k];
            int b   = n >> 18;
            int rem = n & (HH * WW - 1);
            int Y = rem >> 9;
            int X = rem & 511;
            int y0, y1, x0, x1; float fy, fx;
            src_coord(Y, y0, y1, fy);
            src_coord(X, x0, x1, fx);
            const float* base = g_fT + ((size_t)b * SPIX) * DIM;
            const float* p00 = base + ((size_t)(y0 * WF + x0)) * DIM;
            const float* p01 = base + ((size_t)(y0 * WF + x1)) * DIM;
            const float* p10 = base + ((size_t)(y1 * WF + x0)) * DIM;
            const float* p11 = base + ((size_t)(y1 * WF + x1)) * DIM;
            float w00 = (1.f - fy) * (1.f - fx);
            float w01 = (1.f - fy) * fx;
            float w10 = fy * (1.f - fx);
            float w11 = fy * fx;
            float v = w00 * __ldg(p00 + d) + w01 * __ldg(p01 + d)
                    + w10 * __ldg(p10 + d) + w11 * __ldg(p11 + d);
            acc += w * v;
        }
    }
    red[t] = acc;
    __syncthreads();

    // ---- phase E: normalize, EMA, normalize, write ----
    float proto = 0.f;
    if (t < DIM) {
        float tot = red[d] + red[d + 256] + red[d + 512] + red[d + 768];
        proto = tot / fmaxf(wsum, EPSV);
        red2[d] = proto * proto;
    }
    __syncthreads();
    for (int s = 128; s > 0; s >>= 1) {
        if (t < s) red2[t] += red2[t + s];
        __syncthreads();
    }
    float nrm = sqrtf(red2[0]);
    __syncthreads();

    bool has = (L > 0) && (wsum > 0.f);
    float uc = update_count[c];
    float gamma = (uc == 0.f) ? 0.f : fminf(1.f - 1.f / (uc + 1.f), GAMMA_MAX);
    float nv = 0.f;
    if (t < DIM) {
        proto = proto / fmaxf(nrm, EPSV);
        float oldp = prototypes[c * DIM + d];
        nv = has ? (gamma * oldp + (1.f - gamma) * proto) : oldp;
        red2[d] = nv * nv;
    }
    __syncthreads();
    for (int s = 128; s > 0; s >>= 1) {
        if (t < s) red2[t] += red2[t + s];
        __syncthreads();
    }
    float nrm2 = sqrtf(red2[0]);
    if (t < DIM)
        out[c * DIM + d] = nv / fmaxf(nrm2, EPSV);
    if (t == 0) {
        if (out_size >= NC * DIM + NC)
            out[NC * DIM + c] = uc + (has ? 1.f : 0.f);
        g_cnt[c] = 0;   // cleanup for next graph replay
    }
}

// ---------------- launch ----------------
extern "C" void kernel_launch(void* const* d_in, const int* in_sizes, int n_in,
                              void* d_out, int out_size) {
    const float* features     = (const float*)d_in[0];
    const float* weight       = (const float*)d_in[1];
    const float* prototypes   = (const float*)d_in[2];
    const float* update_count = (const float*)d_in[3];
    const int*   labels       = (const int*)d_in[4];
    float* out = (float*)d_out;

    k_main<<<TRANS_BLOCKS + WT_BLOCKS, 256>>>(features, weight, labels);
    k_thresh<<<NC, 256>>>();
    k_tail<<<NC, 1024>>>(prototypes, update_count, out, out_size);
}